// round 16
// baseline (speedup 1.0000x reference)
#include <cuda_runtime.h>
#include <cuda_fp16.h>
#include <cstdint>

#define BATCH 2
#define CIN   64
#define NTOK  9216
#define C1    8
#define NT128 72                  // NTOK / 128
#define NT64  144                 // NTOK / 64
#define NKC   144                 // 64-i chunks (zsum sweep)
#define NKC2  72                  // 128-j chunks (av2 total)
#define NSPLIT 3                  // av2 j-splits
#define NKCS  24                  // NKC2 / NSPLIT
#define LOG2E 1.4426950408889634f
#define ESH   5.770780163555854f  // 4 * log2(e)

// ---------------- scratch ----------------
__device__ float  g_q [BATCH * NTOK * C1];
__device__ __half g_qh[BATCH * NTOK * C1];    // fp16(q * LOG2E)
__device__ __half g_kh[BATCH * NTOK * C1];    // fp16(k)
__device__ __half g_vt[BATCH * CIN * NTOK];   // V'^T fp16: [b][c][j], scaled by 1/64
__device__ float  g_sh[BATCH * NTOK];         // per-j exp2 shift: 6 - ESH - log2(Z')
__device__ float  g_x0[BATCH * CIN * NTOK];   // x partial, j-third 0
__device__ float  g_x1[BATCH * CIN * NTOK];   // x partial, j-third 1
__device__ float  g_x2[BATCH * CIN * NTOK];   // x partial, j-third 2

// ---------------- PTX helpers ----------------
__device__ __forceinline__ uint32_t pack_h2(float lo, float hi) {
    uint32_t r; asm("cvt.rn.f16x2.f32 %0, %1, %2;" : "=r"(r) : "f"(hi), "f"(lo)); return r;
}
__device__ __forceinline__ uint32_t hex2(uint32_t h) {
    uint32_t r; asm("ex2.approx.f16x2 %0, %1;" : "=r"(r) : "r"(h)); return r;
}
__device__ __forceinline__ uint32_t hadd2u(uint32_t a, uint32_t b) {
    uint32_t r; asm("add.f16x2 %0, %1, %2;" : "=r"(r) : "r"(a), "r"(b)); return r;
}
__device__ __forceinline__ float2 h2f2(uint32_t h) {
    float a, b;
    asm("{.reg .f16 l, u; mov.b32 {l, u}, %2; cvt.f32.f16 %0, l; cvt.f32.f16 %1, u;}"
        : "=f"(a), "=f"(b) : "r"(h));
    return make_float2(a, b);
}
__device__ __forceinline__ float lg2f(float x) {
    float r; asm("lg2.approx.f32 %0, %1;" : "=f"(r) : "f"(x)); return r;
}
__device__ __forceinline__ void cp_async16(uint32_t saddr, const void* g) {
    asm volatile("cp.async.cg.shared.global [%0], [%1], 16;\n" :: "r"(saddr), "l"(g));
}
__device__ __forceinline__ void ldsm4(uint32_t& r0, uint32_t& r1, uint32_t& r2, uint32_t& r3,
                                      uint32_t a) {
    asm volatile("ldmatrix.sync.aligned.m8n8.x4.shared.b16 {%0,%1,%2,%3}, [%4];"
                 : "=r"(r0), "=r"(r1), "=r"(r2), "=r"(r3) : "r"(a));
}
__device__ __forceinline__ void mma16816(float& d0, float& d1, float& d2, float& d3,
                                         uint32_t a0, uint32_t a1, uint32_t a2, uint32_t a3,
                                         uint32_t b0, uint32_t b1) {
    asm volatile(
        "mma.sync.aligned.m16n8k16.row.col.f32.f16.f16.f32 "
        "{%0,%1,%2,%3}, {%4,%5,%6,%7}, {%8,%9}, {%0,%1,%2,%3};"
        : "+f"(d0), "+f"(d1), "+f"(d2), "+f"(d3)
        : "r"(a0), "r"(a1), "r"(a2), "r"(a3), "r"(b0), "r"(b1));
}
__device__ __forceinline__ void mma1688(float& d0, float& d1, float& d2, float& d3,
                                        uint32_t a0, uint32_t a1, uint32_t b0) {
    asm volatile(
        "mma.sync.aligned.m16n8k8.row.col.f32.f16.f16.f32 "
        "{%0,%1,%2,%3}, {%4,%5}, {%6}, {%0,%1,%2,%3};"
        : "+f"(d0), "+f"(d1), "+f"(d2), "+f"(d3)
        : "r"(a0), "r"(a1), "r"(b0));
}

// ---------------- K1: q,k 1x1 convs (+ fp16 copies) ----------------
// grid 288: 64 tokens/block, 128 thr = (token, channel half)
__global__ __launch_bounds__(128) void qk_kernel(const float* __restrict__ X,
                          const float* __restrict__ Wq, const float* __restrict__ bq,
                          const float* __restrict__ Wk, const float* __restrict__ bk) {
    __shared__ float sW[16 * CIN];   // [c][o]: o 0-7 = Wq rows, 8-15 = Wk rows
    __shared__ float sred[64][17];
    int tid = threadIdx.x;
    for (int t = tid; t < 16 * CIN; t += 128) {
        int c = t >> 4, o = t & 15;
        sW[t] = (o < 8) ? Wq[o * CIN + c] : Wk[(o - 8) * CIN + c];
    }
    __syncthreads();

    int tl = tid & 63, h = tid >> 6;
    int gi = blockIdx.x * 64 + tl;
    int b = gi / NTOK;
    const float* Xp = X + (size_t)b * CIN * NTOK + (gi - b * NTOK) + (size_t)(h * 32) * NTOK;

    float acc[16];
#pragma unroll
    for (int o = 0; o < 16; o++) acc[o] = 0.f;

#pragma unroll 16
    for (int c = 0; c < 32; c++) {
        float xv = Xp[(size_t)c * NTOK];
        const float4* w4 = (const float4*)&sW[(h * 32 + c) * 16];
        float4 w0 = w4[0], w1 = w4[1], w2 = w4[2], w3 = w4[3];
        acc[0] += w0.x * xv; acc[1] += w0.y * xv; acc[2] += w0.z * xv; acc[3] += w0.w * xv;
        acc[4] += w1.x * xv; acc[5] += w1.y * xv; acc[6] += w1.z * xv; acc[7] += w1.w * xv;
        acc[8] += w2.x * xv; acc[9] += w2.y * xv; acc[10] += w2.z * xv; acc[11] += w2.w * xv;
        acc[12] += w3.x * xv; acc[13] += w3.y * xv; acc[14] += w3.z * xv; acc[15] += w3.w * xv;
    }

    if (h == 1) {
#pragma unroll
        for (int o = 0; o < 16; o++) sred[tl][o] = acc[o];
    }
    __syncthreads();
    if (h == 0) {
        float q[8], k[8];
#pragma unroll
        for (int o = 0; o < 8; o++) {
            q[o] = acc[o] + sred[tl][o] + bq[o];
            k[o] = acc[8 + o] + sred[tl][8 + o] + bk[o];
        }
        float4* qp = (float4*)(g_q + (size_t)gi * C1);
        qp[0] = make_float4(q[0], q[1], q[2], q[3]);
        qp[1] = make_float4(q[4], q[5], q[6], q[7]);
        uint4 qh, kh;
        qh.x = pack_h2(q[0] * LOG2E, q[1] * LOG2E); qh.y = pack_h2(q[2] * LOG2E, q[3] * LOG2E);
        qh.z = pack_h2(q[4] * LOG2E, q[5] * LOG2E); qh.w = pack_h2(q[6] * LOG2E, q[7] * LOG2E);
        *(uint4*)(g_qh + (size_t)gi * C1) = qh;
        kh.x = pack_h2(k[0], k[1]); kh.y = pack_h2(k[2], k[3]);
        kh.z = pack_h2(k[4], k[5]); kh.w = pack_h2(k[6], k[7]);
        *(uint4*)(g_kh + (size_t)gi * C1) = kh;
    }
}

// ---------------- K2: tensor-core Z + shift (64-j strips, grid 288) ----------------
__global__ __launch_bounds__(128, 8) void zsum_kernel() {
    __shared__ __align__(16) char sm[2 * 1024];          // 2-stage Qh: 64 i x 16B
    uint32_t sbase = (uint32_t)__cvta_generic_to_shared(sm);
    int tid = threadIdx.x, lane = tid & 31, warp = tid >> 5;
    int b = blockIdx.x / NT64;
    int j0 = (blockIdx.x - b * NT64) * 64;

    int jrow = j0 + warp * 16 + (lane >> 2);
    const char* khb = (const char*)(g_kh + (size_t)b * NTOK * C1);
    uint32_t a0 = *(const uint32_t*)(khb + (size_t)jrow * 16 + (lane & 3) * 4);
    uint32_t a1 = *(const uint32_t*)(khb + (size_t)(jrow + 8) * 16 + (lane & 3) * 4);

    const uint4* Qh = (const uint4*)(g_qh + (size_t)b * NTOK * C1);
    auto prefetch = [&](int ct, int s) {
        if (tid < 64) cp_async16(sbase + s * 1024 + tid * 16, Qh + ct * 64 + tid);
        asm volatile("cp.async.commit_group;\n" ::: "memory");
    };

    uint32_t kfoff = (lane >> 2) * 16 + (lane & 3) * 4;
    float zfA = 0.f, zfB = 0.f;

    prefetch(0, 0);
    for (int ct = 0; ct < NKC; ct++) {
        int s = ct & 1;
        if (ct + 1 < NKC) prefetch(ct + 1, s ^ 1);
        if (ct + 1 < NKC) asm volatile("cp.async.wait_group 1;\n" ::: "memory");
        else              asm volatile("cp.async.wait_group 0;\n" ::: "memory");
        __syncthreads();

        uint32_t zA = 0, zB = 0;                         // half2 accumulators
#pragma unroll
        for (int t = 0; t < 8; t++) {
            uint32_t bfrag = *(const uint32_t*)(sm + s * 1024 + t * 128 + kfoff);
            float c0 = 0.f, c1 = 0.f, c2 = 0.f, c3 = 0.f;
            mma1688(c0, c1, c2, c3, a0, a1, bfrag);
            zA = hadd2u(zA, hex2(pack_h2(c0 - ESH, c1 - ESH)));
            zB = hadd2u(zB, hex2(pack_h2(c2 - ESH, c3 - ESH)));
        }
        float2 fa = h2f2(zA), fb = h2f2(zB);
        zfA += fa.x + fa.y;
        zfB += fb.x + fb.y;
        __syncthreads();
    }

    zfA += __shfl_xor_sync(0xffffffffu, zfA, 1);
    zfA += __shfl_xor_sync(0xffffffffu, zfA, 2);
    zfB += __shfl_xor_sync(0xffffffffu, zfB, 1);
    zfB += __shfl_xor_sync(0xffffffffu, zfB, 2);
    if ((lane & 3) == 0) {
        g_sh[(size_t)b * NTOK + jrow]     = 6.0f - ESH - lg2f(zfA);
        g_sh[(size_t)b * NTOK + jrow + 8] = 6.0f - ESH - lg2f(zfB);
    }
}

// ---------------- K3: V'^T = (Wv Y + bv)^T / 64  fp16 (64-token strips) ----------------
__global__ __launch_bounds__(256) void vscale_kernel(const float* __restrict__ Y,
                                                     const float* __restrict__ Wv,
                                                     const float* __restrict__ bv) {
    __shared__ float  sW[CIN * CIN];   // [c_in][o]
    __shared__ __half sT[CIN * 64];    // [c][token]
    int tid = threadIdx.x;
    int gj0 = blockIdx.x * 64;
    int b = gj0 / NTOK, j0 = gj0 - b * NTOK;

    for (int t = tid; t < CIN * CIN; t += 256) {
        int c = t >> 6, o = t & 63;
        sW[t] = Wv[o * CIN + c];
    }
    __syncthreads();

    int tl = tid & 63, h = tid >> 6;        // token, channel quarter (16 ch each)

    float acc[16];
#pragma unroll
    for (int o = 0; o < 16; o++) acc[o] = 0.f;

    const float* Yp = Y + (size_t)b * CIN * NTOK + j0 + tl;
#pragma unroll 4
    for (int c = 0; c < CIN; c++) {
        float yv = Yp[(size_t)c * NTOK];
        const float4* w4 = (const float4*)&sW[c * CIN + h * 16];
#pragma unroll
        for (int p = 0; p < 4; p++) {
            float4 w = w4[p];
            acc[p * 4 + 0] += w.x * yv; acc[p * 4 + 1] += w.y * yv;
            acc[p * 4 + 2] += w.z * yv; acc[p * 4 + 3] += w.w * yv;
        }
    }
#pragma unroll
    for (int o = 0; o < 16; o++)
        sT[(h * 16 + o) * 64 + tl] = __float2half((acc[o] + bv[h * 16 + o]) * 0.015625f);
    __syncthreads();

    // 64 c x 64 tokens x 2B = 512 uint4
#pragma unroll
    for (int t = 0; t < 2; t++) {
        int id = tid + t * 256;
        int c = id >> 3, ch = id & 7;
        uint4 v = *(const uint4*)(sT + c * 64 + ch * 8);
        *(uint4*)(g_vt + ((size_t)b * CIN + c) * NTOK + j0 + ch * 8) = v;
    }
}

// ---------------- K4: fused softmax-recompute * V' -> x partial ----------------
// 128-row i-tiles, 128 thr = 4 warps, warp owns TWO m16 row-blocks (32 rows).
// j split 3 ways across blockIdx.z. grid (NT128, BATCH, 3) = 432 blocks.
#define AV_VSTAGE 16384                       // 64 c-rows x 256B (128 j)
#define AV_KOFF   32768                       // 2 V stages
#define AV_KSTAGE 2048                        // Kh: 128 j x 16B
#define AV_SHOFF  36864                       // 32768 + 2*2048
#define AV_SHSTAGE 512                        // sh: 128 j x 4B
#define AV_SMEM   37888

__global__ __launch_bounds__(128) void av2_kernel() {
    extern __shared__ __align__(16) char sm[];
    uint32_t sbase = (uint32_t)__cvta_generic_to_shared(sm);

    int tid = threadIdx.x, lane = tid & 31, warp = tid >> 5;
    int b = blockIdx.y;
    int i0 = blockIdx.x * 128;
    int kt0 = blockIdx.z * NKCS;
    int ktEnd = kt0 + NKCS;

    const __half* Vb = g_vt + (size_t)b * CIN * NTOK;
    const uint4*  Kh = (const uint4*)(g_kh + (size_t)b * NTOK * C1);
    const float*  shb = g_sh + (size_t)b * NTOK;

    // persistent Q A-fragments (m16k8) for two row-blocks, scaled by log2(e)
    int kp = (lane & 3) * 2;
    const float* qb = g_q + (size_t)b * NTOK * C1;
    uint32_t aq[2][2];
#pragma unroll
    for (int rb = 0; rb < 2; rb++) {
        int qrow = i0 + warp * 32 + rb * 16 + (lane >> 2);
        aq[rb][0] = pack_h2(qb[(size_t)qrow * C1 + kp] * LOG2E,
                            qb[(size_t)qrow * C1 + kp + 1] * LOG2E);
        aq[rb][1] = pack_h2(qb[(size_t)(qrow + 8) * C1 + kp] * LOG2E,
                            qb[(size_t)(qrow + 8) * C1 + kp + 1] * LOG2E);
    }

    auto prefetch = [&](int kt, int s) {
        int j0c = kt * 128;
#pragma unroll
        for (int cc = 0; cc < 8; cc++) {                 // V: 64 c-rows x 16 chunks
            int id = tid + cc * 128;
            int row = id >> 4, ch = id & 15;
            cp_async16(sbase + s * AV_VSTAGE + row * 256 + ((ch ^ (row & 7)) << 4),
                       Vb + (size_t)row * NTOK + j0c + ch * 8);
        }
        cp_async16(sbase + AV_KOFF + s * AV_KSTAGE + tid * 16, Kh + j0c + tid);
        if (tid < 32)
            cp_async16(sbase + AV_SHOFF + s * AV_SHSTAGE + tid * 16, shb + j0c + tid * 4);
        asm volatile("cp.async.commit_group;\n" ::: "memory");
    };

    float d[2][8][4];
#pragma unroll
    for (int rb = 0; rb < 2; rb++)
#pragma unroll
        for (int ni = 0; ni < 8; ni++)
#pragma unroll
            for (int p = 0; p < 4; p++) d[rb][ni][p] = 0.f;

    int brow[4];
#pragma unroll
    for (int nb = 0; nb < 4; nb++)
        brow[nb] = nb * 16 + ((lane >> 4) << 3) + (lane & 7);
    int bchs = (lane >> 3) & 1;
    uint32_t kfoff  = (lane >> 2) * 16 + (lane & 3) * 4;
    uint32_t shloff = (lane & 3) * 8;

    prefetch(kt0, 0);

    for (int kt = kt0; kt < ktEnd; kt++) {
        int s = kt & 1;
        if (kt + 1 < ktEnd) prefetch(kt + 1, s ^ 1);
        if (kt + 1 < ktEnd) asm volatile("cp.async.wait_group 1;\n" ::: "memory");
        else                asm volatile("cp.async.wait_group 0;\n" ::: "memory");
        __syncthreads();

        const char* kB  = sm + AV_KOFF + s * AV_KSTAGE;
        const char* shB = sm + AV_SHOFF + s * AV_SHSTAGE;
        uint32_t vBase = sbase + s * AV_VSTAGE;

        // process 128-j chunk in two 64-j halves to bound register pressure
#pragma unroll
        for (int hh = 0; hh < 2; hh++) {
            // ---- S-tiles for both row-blocks; shift folded via C-fragment init ----
            uint32_t pa[2][4][4];
#pragma unroll
            for (int tl = 0; tl < 8; tl++) {
                int t = hh * 8 + tl;
                uint32_t bfrag = *(const uint32_t*)(kB + t * 128 + kfoff);
                float2 shv = *(const float2*)(shB + t * 32 + shloff);
#pragma unroll
                for (int rb = 0; rb < 2; rb++) {
                    float c0 = shv.x, c1 = shv.y, c2 = shv.x, c3 = shv.y;
                    mma1688(c0, c1, c2, c3, aq[rb][0], aq[rb][1], bfrag);
                    pa[rb][tl >> 1][(tl & 1) * 2 + 0] = hex2(pack_h2(c0, c1));
                    pa[rb][tl >> 1][(tl & 1) * 2 + 1] = hex2(pack_h2(c2, c3));
                }
            }

            // ---- AV: each B fragment feeds both row-blocks ----
#pragma unroll
            for (int l = 0; l < 4; l++) {
                int ks = hh * 4 + l;
                uint32_t br[4][4];
                int ch = ks * 2 + bchs;
#pragma unroll
                for (int nb = 0; nb < 4; nb++)
                    ldsm4(br[nb][0], br[nb][1], br[nb][2], br[nb][3],
                          vBase + brow[nb] * 256 + ((ch ^ (brow[nb] & 7)) << 4));
#pragma unroll
                for (int rb = 0; rb < 2; rb++)
#pragma unroll
                    for (int ni = 0; ni < 8; ni++) {
                        int nb = ni >> 1, sub = ni & 1;
                        mma16816(d[rb][ni][0], d[rb][ni][1], d[rb][ni][2], d[rb][ni][3],
                                 pa[rb][l][0], pa[rb][l][1], pa[rb][l][2], pa[rb][l][3],
                                 br[nb][sub * 2], br[nb][sub * 2 + 1]);
                    }
            }
        }
        __syncthreads();
    }

    // ---- epilogue: transpose via padded smem, write f32 partial ----
    float* sX = (float*)sm;                 // [64 c][132]
#pragma unroll
    for (int rb = 0; rb < 2; rb++)
#pragma unroll
        for (int ni = 0; ni < 8; ni++) {
            int r = warp * 32 + rb * 16 + (lane >> 2);
            int c = ni * 8 + (lane & 3) * 2;
            sX[c * 132 + r]           = d[rb][ni][0];
            sX[(c + 1) * 132 + r]     = d[rb][ni][1];
            sX[c * 132 + r + 8]       = d[rb][ni][2];
            sX[(c + 1) * 132 + r + 8] = d[rb][ni][3];
        }
    __syncthreads();

    float* xbase = (blockIdx.z == 0) ? g_x0 : (blockIdx.z == 1 ? g_x1 : g_x2);
    float* xp = xbase + (size_t)b * CIN * NTOK + i0;
#pragma unroll
    for (int t = 0; t < 16; t++) {
        int id = tid + t * 128;             // 2048 float4s (64 c x 32)
        int c = id >> 5, q4 = id & 31;
        const float* sp = sX + c * 132 + q4 * 4;
        float4 o;
        o.x = sp[0]; o.y = sp[1]; o.z = sp[2]; o.w = sp[3];
        *(float4*)(xp + (size_t)c * NTOK + q4 * 4) = o;
    }
}

// ---------------- K5: out = Y + x0 + x1 + x2 ----------------
__global__ __launch_bounds__(256) void merge_kernel(const float* __restrict__ Y,
                                                    float* __restrict__ out) {
    int id = blockIdx.x * 256 + threadIdx.x;      // float4 index
    float4 y = ((const float4*)Y)[id];
    float4 a = ((const float4*)g_x0)[id];
    float4 c = ((const float4*)g_x1)[id];
    float4 e = ((const float4*)g_x2)[id];
    float4 o;
    o.x = y.x + a.x + c.x + e.x; o.y = y.y + a.y + c.y + e.y;
    o.z = y.z + a.z + c.z + e.z; o.w = y.w + a.w + c.w + e.w;
    ((float4*)out)[id] = o;
}

// ---------------- launch (stream-forked: vscale overlaps qk+zsum) ----------------
extern "C" void kernel_launch(void* const* d_in, const int* in_sizes, int n_in,
                              void* d_out, int out_size) {
    const float* X  = (const float*)d_in[0];
    const float* Y  = (const float*)d_in[1];
    const float* Wq = (const float*)d_in[2];
    const float* bq = (const float*)d_in[3];
    const float* Wk = (const float*)d_in[4];
    const float* bk = (const float*)d_in[5];
    const float* Wv = (const float*)d_in[6];
    const float* bv = (const float*)d_in[7];
    float* out = (float*)d_out;

    static cudaStream_t s2 = nullptr;
    static cudaEvent_t evFork = nullptr, evJoin = nullptr;
    if (s2 == nullptr) {
        cudaStreamCreateWithFlags(&s2, cudaStreamNonBlocking);
        cudaEventCreateWithFlags(&evFork, cudaEventDisableTiming);
        cudaEventCreateWithFlags(&evJoin, cudaEventDisableTiming);
        cudaFuncSetAttribute(av2_kernel, cudaFuncAttributeMaxDynamicSharedMemorySize,
                             AV_SMEM);
    }

    // fork: vscale (depends only on Y) runs on s2 concurrently with qk -> zsum
    cudaEventRecord(evFork, 0);
    cudaStreamWaitEvent(s2, evFork, 0);
    vscale_kernel<<<BATCH * NT64, 256, 0, s2>>>(Y, Wv, bv);
    cudaEventRecord(evJoin, s2);

    qk_kernel<<<BATCH * NT64, 128>>>(X, Wq, bq, Wk, bk);
    zsum_kernel<<<BATCH * NT64, 128>>>();

    // join: av2 needs vscale's g_vt as well as zsum's g_sh
    cudaStreamWaitEvent(0, evJoin, 0);
    av2_kernel<<<dim3(NT128, BATCH, NSPLIT), 128, AV_SMEM>>>();
    merge_kernel<<<BATCH * CIN * NTOK / 1024, 256>>>(Y, out);
}

// round 17
// speedup vs baseline: 1.1796x; 1.1796x over previous
#include <cuda_runtime.h>
#include <cuda_fp16.h>
#include <cstdint>

#define BATCH 2
#define CIN   64
#define NTOK  9216
#define C1    8
#define NT128 72                  // NTOK / 128
#define NT64  144                 // NTOK / 64
#define NKC2  72                  // 128-wide chunks (zsum i-sweep and av2 j-sweep)
#define NSPLIT 3                  // av2 j-splits
#define NKCS  24                  // NKC2 / NSPLIT
#define LOG2E 1.4426950408889634f
#define ESH   5.770780163555854f  // 4 * log2(e)

// ---------------- scratch ----------------
__device__ float  g_q [BATCH * NTOK * C1];
__device__ __half g_qh[BATCH * NTOK * C1];    // fp16(q * LOG2E)
__device__ __half g_kh[BATCH * NTOK * C1];    // fp16(k)
__device__ __half g_vt[BATCH * CIN * NTOK];   // V'^T fp16: [b][c][j], scaled by 1/64
__device__ float  g_sh[BATCH * NTOK];         // per-j exp2 shift: 6 - ESH - log2(Z')
__device__ float  g_x0[BATCH * CIN * NTOK];   // x partial, j-third 0
__device__ float  g_x1[BATCH * CIN * NTOK];   // x partial, j-third 1
__device__ float  g_x2[BATCH * CIN * NTOK];   // x partial, j-third 2

// ---------------- PTX helpers ----------------
__device__ __forceinline__ uint32_t pack_h2(float lo, float hi) {
    uint32_t r; asm("cvt.rn.f16x2.f32 %0, %1, %2;" : "=r"(r) : "f"(hi), "f"(lo)); return r;
}
__device__ __forceinline__ uint32_t hex2(uint32_t h) {
    uint32_t r; asm("ex2.approx.f16x2 %0, %1;" : "=r"(r) : "r"(h)); return r;
}
__device__ __forceinline__ uint32_t hadd2u(uint32_t a, uint32_t b) {
    uint32_t r; asm("add.f16x2 %0, %1, %2;" : "=r"(r) : "r"(a), "r"(b)); return r;
}
__device__ __forceinline__ float2 h2f2(uint32_t h) {
    float a, b;
    asm("{.reg .f16 l, u; mov.b32 {l, u}, %2; cvt.f32.f16 %0, l; cvt.f32.f16 %1, u;}"
        : "=f"(a), "=f"(b) : "r"(h));
    return make_float2(a, b);
}
__device__ __forceinline__ float lg2f(float x) {
    float r; asm("lg2.approx.f32 %0, %1;" : "=f"(r) : "f"(x)); return r;
}
__device__ __forceinline__ void cp_async16(uint32_t saddr, const void* g) {
    asm volatile("cp.async.cg.shared.global [%0], [%1], 16;\n" :: "r"(saddr), "l"(g));
}
__device__ __forceinline__ void ldsm4(uint32_t& r0, uint32_t& r1, uint32_t& r2, uint32_t& r3,
                                      uint32_t a) {
    asm volatile("ldmatrix.sync.aligned.m8n8.x4.shared.b16 {%0,%1,%2,%3}, [%4];"
                 : "=r"(r0), "=r"(r1), "=r"(r2), "=r"(r3) : "r"(a));
}
__device__ __forceinline__ void mma16816(float& d0, float& d1, float& d2, float& d3,
                                         uint32_t a0, uint32_t a1, uint32_t a2, uint32_t a3,
                                         uint32_t b0, uint32_t b1) {
    asm volatile(
        "mma.sync.aligned.m16n8k16.row.col.f32.f16.f16.f32 "
        "{%0,%1,%2,%3}, {%4,%5,%6,%7}, {%8,%9}, {%0,%1,%2,%3};"
        : "+f"(d0), "+f"(d1), "+f"(d2), "+f"(d3)
        : "r"(a0), "r"(a1), "r"(a2), "r"(a3), "r"(b0), "r"(b1));
}
__device__ __forceinline__ void mma1688(float& d0, float& d1, float& d2, float& d3,
                                        uint32_t a0, uint32_t a1, uint32_t b0) {
    asm volatile(
        "mma.sync.aligned.m16n8k8.row.col.f32.f16.f16.f32 "
        "{%0,%1,%2,%3}, {%4,%5}, {%6}, {%0,%1,%2,%3};"
        : "+f"(d0), "+f"(d1), "+f"(d2), "+f"(d3)
        : "r"(a0), "r"(a1), "r"(b0));
}

// ---------------- K1: q,k 1x1 convs (+ fp16 copies) ----------------
// grid 288: 64 tokens/block, 128 thr = (token, channel half)
__global__ __launch_bounds__(128) void qk_kernel(const float* __restrict__ X,
                          const float* __restrict__ Wq, const float* __restrict__ bq,
                          const float* __restrict__ Wk, const float* __restrict__ bk) {
    __shared__ float sW[16 * CIN];   // [c][o]: o 0-7 = Wq rows, 8-15 = Wk rows
    __shared__ float sred[64][17];
    int tid = threadIdx.x;
    for (int t = tid; t < 16 * CIN; t += 128) {
        int c = t >> 4, o = t & 15;
        sW[t] = (o < 8) ? Wq[o * CIN + c] : Wk[(o - 8) * CIN + c];
    }
    __syncthreads();

    int tl = tid & 63, h = tid >> 6;
    int gi = blockIdx.x * 64 + tl;
    int b = gi / NTOK;
    const float* Xp = X + (size_t)b * CIN * NTOK + (gi - b * NTOK) + (size_t)(h * 32) * NTOK;

    float acc[16];
#pragma unroll
    for (int o = 0; o < 16; o++) acc[o] = 0.f;

#pragma unroll 16
    for (int c = 0; c < 32; c++) {
        float xv = Xp[(size_t)c * NTOK];
        const float4* w4 = (const float4*)&sW[(h * 32 + c) * 16];
        float4 w0 = w4[0], w1 = w4[1], w2 = w4[2], w3 = w4[3];
        acc[0] += w0.x * xv; acc[1] += w0.y * xv; acc[2] += w0.z * xv; acc[3] += w0.w * xv;
        acc[4] += w1.x * xv; acc[5] += w1.y * xv; acc[6] += w1.z * xv; acc[7] += w1.w * xv;
        acc[8] += w2.x * xv; acc[9] += w2.y * xv; acc[10] += w2.z * xv; acc[11] += w2.w * xv;
        acc[12] += w3.x * xv; acc[13] += w3.y * xv; acc[14] += w3.z * xv; acc[15] += w3.w * xv;
    }

    if (h == 1) {
#pragma unroll
        for (int o = 0; o < 16; o++) sred[tl][o] = acc[o];
    }
    __syncthreads();
    if (h == 0) {
        float q[8], k[8];
#pragma unroll
        for (int o = 0; o < 8; o++) {
            q[o] = acc[o] + sred[tl][o] + bq[o];
            k[o] = acc[8 + o] + sred[tl][8 + o] + bk[o];
        }
        float4* qp = (float4*)(g_q + (size_t)gi * C1);
        qp[0] = make_float4(q[0], q[1], q[2], q[3]);
        qp[1] = make_float4(q[4], q[5], q[6], q[7]);
        uint4 qh, kh;
        qh.x = pack_h2(q[0] * LOG2E, q[1] * LOG2E); qh.y = pack_h2(q[2] * LOG2E, q[3] * LOG2E);
        qh.z = pack_h2(q[4] * LOG2E, q[5] * LOG2E); qh.w = pack_h2(q[6] * LOG2E, q[7] * LOG2E);
        *(uint4*)(g_qh + (size_t)gi * C1) = qh;
        kh.x = pack_h2(k[0], k[1]); kh.y = pack_h2(k[2], k[3]);
        kh.z = pack_h2(k[4], k[5]); kh.w = pack_h2(k[6], k[7]);
        *(uint4*)(g_kh + (size_t)gi * C1) = kh;
    }
}

// ---------------- K2: fused V' conv + tensor-core Z (64-j strips, grid 288) ----------------
// Part A (vscale): V' = (Wv Y + bv)/64 -> g_vt   (FMA/load-bound)
// Part B (zsum):   Z_j over all i -> g_sh        (MUFU-bound), 128-i chunks
__global__ __launch_bounds__(128) void zsumv_kernel(const float* __restrict__ Y,
                                                    const float* __restrict__ Wv,
                                                    const float* __restrict__ bv) {
    __shared__ __align__(16) char sm[2 * 2048];          // 2-stage Qh: 128 i x 16B
    __shared__ float  sWv[CIN * CIN];                    // [c_in][o] 16KB
    __shared__ __half sT[CIN * 64];                      // [c][token] 8KB
    uint32_t sbase = (uint32_t)__cvta_generic_to_shared(sm);
    int tid = threadIdx.x, lane = tid & 31, warp = tid >> 5;
    int b = blockIdx.x / NT64;
    int j0 = (blockIdx.x - b * NT64) * 64;

    // Kh fragments for part B (issue loads early)
    int jrow = j0 + warp * 16 + (lane >> 2);
    const char* khb = (const char*)(g_kh + (size_t)b * NTOK * C1);
    uint32_t a0 = *(const uint32_t*)(khb + (size_t)jrow * 16 + (lane & 3) * 4);
    uint32_t a1 = *(const uint32_t*)(khb + (size_t)(jrow + 8) * 16 + (lane & 3) * 4);

    for (int t = tid; t < CIN * CIN; t += 128) {
        int c = t >> 6, o = t & 63;
        sWv[t] = Wv[o * CIN + c];
    }
    __syncthreads();

    // ---- part A: vscale ----
    {
        int tl = tid & 63, h = tid >> 6;        // token, channel half (32 ch each)
        float acc[32];
#pragma unroll
        for (int o = 0; o < 32; o++) acc[o] = 0.f;

        const float* Yp = Y + (size_t)b * CIN * NTOK + j0 + tl;
#pragma unroll 2
        for (int c = 0; c < CIN; c++) {
            float yv = Yp[(size_t)c * NTOK];
            const float4* w4 = (const float4*)&sWv[c * CIN + h * 32];
#pragma unroll
            for (int p = 0; p < 8; p++) {
                float4 w = w4[p];
                acc[p * 4 + 0] += w.x * yv; acc[p * 4 + 1] += w.y * yv;
                acc[p * 4 + 2] += w.z * yv; acc[p * 4 + 3] += w.w * yv;
            }
        }
#pragma unroll
        for (int o = 0; o < 32; o++)
            sT[(h * 32 + o) * 64 + tl] = __float2half((acc[o] + bv[h * 32 + o]) * 0.015625f);
        __syncthreads();

        // 64 c x 64 tokens x 2B = 512 uint4, 128 threads -> 4 iters
#pragma unroll
        for (int t = 0; t < 4; t++) {
            int id = tid + t * 128;
            int c = id >> 3, ch = id & 7;
            uint4 v = *(const uint4*)(sT + c * 64 + ch * 8);
            *(uint4*)(g_vt + ((size_t)b * CIN + c) * NTOK + j0 + ch * 8) = v;
        }
    }

    // ---- part B: zsum, 128-i chunks (72 iterations) ----
    const uint4* Qh = (const uint4*)(g_qh + (size_t)b * NTOK * C1);
    auto prefetch = [&](int ct, int s) {
        cp_async16(sbase + s * 2048 + tid * 16, Qh + ct * 128 + tid);
        asm volatile("cp.async.commit_group;\n" ::: "memory");
    };

    uint32_t kfoff = (lane >> 2) * 16 + (lane & 3) * 4;
    float zfA = 0.f, zfB = 0.f;

    prefetch(0, 0);
    for (int ct = 0; ct < NKC2; ct++) {
        int s = ct & 1;
        if (ct + 1 < NKC2) prefetch(ct + 1, s ^ 1);
        if (ct + 1 < NKC2) asm volatile("cp.async.wait_group 1;\n" ::: "memory");
        else               asm volatile("cp.async.wait_group 0;\n" ::: "memory");
        __syncthreads();

        uint32_t zA = 0, zB = 0;                         // half2 accumulators
#pragma unroll
        for (int t = 0; t < 16; t++) {
            uint32_t bfrag = *(const uint32_t*)(sm + s * 2048 + t * 128 + kfoff);
            float c0 = 0.f, c1 = 0.f, c2 = 0.f, c3 = 0.f;
            mma1688(c0, c1, c2, c3, a0, a1, bfrag);
            zA = hadd2u(zA, hex2(pack_h2(c0 - ESH, c1 - ESH)));
            zB = hadd2u(zB, hex2(pack_h2(c2 - ESH, c3 - ESH)));
        }
        float2 fa = h2f2(zA), fb = h2f2(zB);
        zfA += fa.x + fa.y;
        zfB += fb.x + fb.y;
        __syncthreads();
    }

    zfA += __shfl_xor_sync(0xffffffffu, zfA, 1);
    zfA += __shfl_xor_sync(0xffffffffu, zfA, 2);
    zfB += __shfl_xor_sync(0xffffffffu, zfB, 1);
    zfB += __shfl_xor_sync(0xffffffffu, zfB, 2);
    if ((lane & 3) == 0) {
        g_sh[(size_t)b * NTOK + jrow]     = 6.0f - ESH - lg2f(zfA);
        g_sh[(size_t)b * NTOK + jrow + 8] = 6.0f - ESH - lg2f(zfB);
    }
}

// ---------------- K3: fused softmax-recompute * V' -> x partial ----------------
// 128-row i-tiles, 128 thr = 4 warps, warp owns TWO m16 row-blocks (32 rows).
// j split 3 ways across blockIdx.z. grid (NT128, BATCH, 3) = 432 blocks.
#define AV_VSTAGE 16384                       // 64 c-rows x 256B (128 j)
#define AV_KOFF   32768                       // 2 V stages
#define AV_KSTAGE 2048                        // Kh: 128 j x 16B
#define AV_SHOFF  36864                       // 32768 + 2*2048
#define AV_SHSTAGE 512                        // sh: 128 j x 4B
#define AV_SMEM   37888

__global__ __launch_bounds__(128) void av2_kernel() {
    extern __shared__ __align__(16) char sm[];
    uint32_t sbase = (uint32_t)__cvta_generic_to_shared(sm);

    int tid = threadIdx.x, lane = tid & 31, warp = tid >> 5;
    int b = blockIdx.y;
    int i0 = blockIdx.x * 128;
    int kt0 = blockIdx.z * NKCS;
    int ktEnd = kt0 + NKCS;

    const __half* Vb = g_vt + (size_t)b * CIN * NTOK;
    const uint4*  Kh = (const uint4*)(g_kh + (size_t)b * NTOK * C1);
    const float*  shb = g_sh + (size_t)b * NTOK;

    // persistent Q A-fragments (m16k8) for two row-blocks, scaled by log2(e)
    int kp = (lane & 3) * 2;
    const float* qb = g_q + (size_t)b * NTOK * C1;
    uint32_t aq[2][2];
#pragma unroll
    for (int rb = 0; rb < 2; rb++) {
        int qrow = i0 + warp * 32 + rb * 16 + (lane >> 2);
        aq[rb][0] = pack_h2(qb[(size_t)qrow * C1 + kp] * LOG2E,
                            qb[(size_t)qrow * C1 + kp + 1] * LOG2E);
        aq[rb][1] = pack_h2(qb[(size_t)(qrow + 8) * C1 + kp] * LOG2E,
                            qb[(size_t)(qrow + 8) * C1 + kp + 1] * LOG2E);
    }

    auto prefetch = [&](int kt, int s) {
        int j0c = kt * 128;
#pragma unroll
        for (int cc = 0; cc < 8; cc++) {                 // V: 64 c-rows x 16 chunks
            int id = tid + cc * 128;
            int row = id >> 4, ch = id & 15;
            cp_async16(sbase + s * AV_VSTAGE + row * 256 + ((ch ^ (row & 7)) << 4),
                       Vb + (size_t)row * NTOK + j0c + ch * 8);
        }
        cp_async16(sbase + AV_KOFF + s * AV_KSTAGE + tid * 16, Kh + j0c + tid);
        if (tid < 32)
            cp_async16(sbase + AV_SHOFF + s * AV_SHSTAGE + tid * 16, shb + j0c + tid * 4);
        asm volatile("cp.async.commit_group;\n" ::: "memory");
    };

    float d[2][8][4];
#pragma unroll
    for (int rb = 0; rb < 2; rb++)
#pragma unroll
        for (int ni = 0; ni < 8; ni++)
#pragma unroll
            for (int p = 0; p < 4; p++) d[rb][ni][p] = 0.f;

    int brow[4];
#pragma unroll
    for (int nb = 0; nb < 4; nb++)
        brow[nb] = nb * 16 + ((lane >> 4) << 3) + (lane & 7);
    int bchs = (lane >> 3) & 1;
    uint32_t kfoff  = (lane >> 2) * 16 + (lane & 3) * 4;
    uint32_t shloff = (lane & 3) * 8;

    prefetch(kt0, 0);

    for (int kt = kt0; kt < ktEnd; kt++) {
        int s = kt & 1;
        if (kt + 1 < ktEnd) prefetch(kt + 1, s ^ 1);
        if (kt + 1 < ktEnd) asm volatile("cp.async.wait_group 1;\n" ::: "memory");
        else                asm volatile("cp.async.wait_group 0;\n" ::: "memory");
        __syncthreads();

        const char* kB  = sm + AV_KOFF + s * AV_KSTAGE;
        const char* shB = sm + AV_SHOFF + s * AV_SHSTAGE;
        uint32_t vBase = sbase + s * AV_VSTAGE;

        // process 128-j chunk in two 64-j halves to bound register pressure
#pragma unroll
        for (int hh = 0; hh < 2; hh++) {
            // ---- S-tiles for both row-blocks; shift folded via C-fragment init ----
            uint32_t pa[2][4][4];
#pragma unroll
            for (int tl = 0; tl < 8; tl++) {
                int t = hh * 8 + tl;
                uint32_t bfrag = *(const uint32_t*)(kB + t * 128 + kfoff);
                float2 shv = *(const float2*)(shB + t * 32 + shloff);
#pragma unroll
                for (int rb = 0; rb < 2; rb++) {
                    float c0 = shv.x, c1 = shv.y, c2 = shv.x, c3 = shv.y;
                    mma1688(c0, c1, c2, c3, aq[rb][0], aq[rb][1], bfrag);
                    pa[rb][tl >> 1][(tl & 1) * 2 + 0] = hex2(pack_h2(c0, c1));
                    pa[rb][tl >> 1][(tl & 1) * 2 + 1] = hex2(pack_h2(c2, c3));
                }
            }

            // ---- AV: each B fragment feeds both row-blocks ----
#pragma unroll
            for (int l = 0; l < 4; l++) {
                int ks = hh * 4 + l;
                uint32_t br[4][4];
                int ch = ks * 2 + bchs;
#pragma unroll
                for (int nb = 0; nb < 4; nb++)
                    ldsm4(br[nb][0], br[nb][1], br[nb][2], br[nb][3],
                          vBase + brow[nb] * 256 + ((ch ^ (brow[nb] & 7)) << 4));
#pragma unroll
                for (int rb = 0; rb < 2; rb++)
#pragma unroll
                    for (int ni = 0; ni < 8; ni++) {
                        int nb = ni >> 1, sub = ni & 1;
                        mma16816(d[rb][ni][0], d[rb][ni][1], d[rb][ni][2], d[rb][ni][3],
                                 pa[rb][l][0], pa[rb][l][1], pa[rb][l][2], pa[rb][l][3],
                                 br[nb][sub * 2], br[nb][sub * 2 + 1]);
                    }
            }
        }
        __syncthreads();
    }

    // ---- epilogue: transpose via padded smem, write f32 partial ----
    float* sX = (float*)sm;                 // [64 c][132]
#pragma unroll
    for (int rb = 0; rb < 2; rb++)
#pragma unroll
        for (int ni = 0; ni < 8; ni++) {
            int r = warp * 32 + rb * 16 + (lane >> 2);
            int c = ni * 8 + (lane & 3) * 2;
            sX[c * 132 + r]           = d[rb][ni][0];
            sX[(c + 1) * 132 + r]     = d[rb][ni][1];
            sX[c * 132 + r + 8]       = d[rb][ni][2];
            sX[(c + 1) * 132 + r + 8] = d[rb][ni][3];
        }
    __syncthreads();

    float* xbase = (blockIdx.z == 0) ? g_x0 : (blockIdx.z == 1 ? g_x1 : g_x2);
    float* xp = xbase + (size_t)b * CIN * NTOK + i0;
#pragma unroll
    for (int t = 0; t < 16; t++) {
        int id = tid + t * 128;             // 2048 float4s (64 c x 32)
        int c = id >> 5, q4 = id & 31;
        const float* sp = sX + c * 132 + q4 * 4;
        float4 o;
        o.x = sp[0]; o.y = sp[1]; o.z = sp[2]; o.w = sp[3];
        *(float4*)(xp + (size_t)c * NTOK + q4 * 4) = o;
    }
}

// ---------------- K4: out = Y + x0 + x1 + x2 ----------------
__global__ __launch_bounds__(256) void merge_kernel(const float* __restrict__ Y,
                                                    float* __restrict__ out) {
    int id = blockIdx.x * 256 + threadIdx.x;      // float4 index
    float4 y = ((const float4*)Y)[id];
    float4 a = ((const float4*)g_x0)[id];
    float4 c = ((const float4*)g_x1)[id];
    float4 e = ((const float4*)g_x2)[id];
    float4 o;
    o.x = y.x + a.x + c.x + e.x; o.y = y.y + a.y + c.y + e.y;
    o.z = y.z + a.z + c.z + e.z; o.w = y.w + a.w + c.w + e.w;
    ((float4*)out)[id] = o;
}

// ---------------- launch ----------------
extern "C" void kernel_launch(void* const* d_in, const int* in_sizes, int n_in,
                              void* d_out, int out_size) {
    const float* X  = (const float*)d_in[0];
    const float* Y  = (const float*)d_in[1];
    const float* Wq = (const float*)d_in[2];
    const float* bq = (const float*)d_in[3];
    const float* Wk = (const float*)d_in[4];
    const float* bk = (const float*)d_in[5];
    const float* Wv = (const float*)d_in[6];
    const float* bv = (const float*)d_in[7];
    float* out = (float*)d_out;

    cudaFuncSetAttribute(av2_kernel, cudaFuncAttributeMaxDynamicSharedMemorySize, AV_SMEM);

    qk_kernel<<<BATCH * NT64, 128>>>(X, Wq, bq, Wk, bk);
    zsumv_kernel<<<BATCH * NT64, 128>>>(Y, Wv, bv);
    av2_kernel<<<dim3(NT128, BATCH, NSPLIT), 128, AV_SMEM>>>();
    merge_kernel<<<BATCH * CIN * NTOK / 1024, 256>>>(Y, out);
}